// round 1
// baseline (speedup 1.0000x reference)
#include <cuda_runtime.h>
#include <cstdint>
#include <cstddef>

// Problem constants
#define Bb   16
#define Nn   4096
#define Dd   256
#define Kk   512
#define ROWS (Bb * Nn)        // 65536
#define TM   64               // rows per block
#define TK   128              // codes per k-chunk
#define TD   64               // dims per d-chunk
#define ZP   68               // z smem pitch (rows dim), multiple of 4, != 64 to break bank conflicts
#define CP   132              // codebook smem pitch (codes dim), multiple of 4
#define NBLK (ROWS / TM)      // 1024

// Scratch device globals (no allocation allowed)
__device__ double g_loss;
__device__ int    g_mflag;     // bit0: non-{0,1} int pattern => packed bool bytes; bit1: float 1.0f pattern
__device__ float  g_esq[Kk];

__global__ void init_k() {
    g_loss  = 0.0;
    g_mflag = 0;
}

// Classify mask dtype from raw bytes. Reads only first ROWS/4 32-bit words,
// which is in-bounds for bool (ROWS bytes), int32 (4*ROWS bytes), float32.
__global__ void detect_k(const unsigned int* __restrict__ m) {
    int i = blockIdx.x * blockDim.x + threadIdx.x;
    int flags = 0;
    for (int idx = i; idx < (ROWS / 4); idx += gridDim.x * blockDim.x) {
        unsigned int v = m[idx];
        if (v == 0x3F800000u) flags |= 2;      // float 1.0f
        else if (v > 1u)      flags |= 1;      // packed bool bytes (e.g. 0x00010101)
    }
    if (flags) atomicOr(&g_mflag, flags);
}

__global__ void esq_k(const float* __restrict__ cb) {
    int k = blockIdx.x * blockDim.x + threadIdx.x;
    if (k < Kk) {
        const float* p = cb + (size_t)k * Dd;
        float s = 0.f;
#pragma unroll 8
        for (int d = 0; d < Dd; ++d) s += p[d] * p[d];
        g_esq[k] = s;
    }
}

__device__ __forceinline__ int read_mask(const void* m, int n, int flag) {
    if (flag & 2) return ((const float*)m)[n] != 0.0f;
    if (flag & 1) return ((const unsigned char*)m)[n] != 0;
    return ((const int*)m)[n] != 0;
}

// Main VQ kernel: 64 rows/CTA, full K per CTA, D chunked by 64.
// 256 threads: thread = (rg, cg), rg=tid>>4 handles rows 4*rg..4*rg+3,
// cg=tid&15 handles codes 8*cg..8*cg+7 within each 128-code chunk.
__global__ __launch_bounds__(256, 2) void vq_main(
    const float* __restrict__ z,
    const void*  __restrict__ mask,
    const float* __restrict__ cb,
    float* __restrict__ out_q,
    float* __restrict__ out_i,
    int write_idx)
{
    extern __shared__ float sh[];
    float* zs  = sh;                 // [Dd][ZP]  (d-major, row within pitch)
    float* cbs = sh + Dd * ZP;       // [TD][CP]  (d-major, code within pitch)

    const int tid = threadIdx.x;
    const int rg  = tid >> 4;        // 0..15
    const int cg  = tid & 15;        // 0..15
    const int r0  = blockIdx.x * TM;
    const int mflag = g_mflag;

    // Load z tile, transposed: zs[d*ZP + row_local]
    for (int it = 0; it < TM; ++it) {
        zs[tid * ZP + it] = z[(size_t)(r0 + it) * Dd + tid];
    }

    float bs[4];
    int   bk[4];
#pragma unroll
    for (int r = 0; r < 4; ++r) { bs[r] = 3.4e38f; bk[r] = 0; }

    for (int kc = 0; kc < Kk / TK; ++kc) {
        float acc[4][8];
#pragma unroll
        for (int r = 0; r < 4; ++r)
#pragma unroll
            for (int c = 0; c < 8; ++c) acc[r][c] = 0.f;

        for (int dc = 0; dc < Dd / TD; ++dc) {
            __syncthreads();
            // Load codebook chunk [TK codes][TD dims] -> cbs[d*CP + j]
            {
                const size_t gbase = (size_t)(kc * TK) * Dd + dc * TD;
                for (int t = tid; t < TD * TK; t += 256) {
                    int j = t >> 6;        // code within chunk (varies slowly)
                    int d = t & 63;        // dim (contiguous across threads -> coalesced)
                    cbs[d * CP + j] = cb[gbase + (size_t)j * Dd + d];
                }
            }
            __syncthreads();

            const int dbase = dc * TD;
#pragma unroll 8
            for (int d = 0; d < TD; ++d) {
                const float4 zv = *reinterpret_cast<const float4*>(&zs[(dbase + d) * ZP + 4 * rg]);
                const float4 c0 = *reinterpret_cast<const float4*>(&cbs[d * CP + 8 * cg]);
                const float4 c1 = *reinterpret_cast<const float4*>(&cbs[d * CP + 8 * cg + 4]);
                float zr[4] = {zv.x, zv.y, zv.z, zv.w};
                float cc[8] = {c0.x, c0.y, c0.z, c0.w, c1.x, c1.y, c1.z, c1.w};
#pragma unroll
                for (int r = 0; r < 4; ++r)
#pragma unroll
                    for (int c = 0; c < 8; ++c)
                        acc[r][c] = fmaf(zr[r], cc[c], acc[r][c]);
            }
        }

        // Fold this k-chunk into running argmin (score = e_sq - 2*dot; z_sq is row-constant)
#pragma unroll
        for (int c = 0; c < 8; ++c) {
            int k = kc * TK + 8 * cg + c;
            float eq = g_esq[k];
#pragma unroll
            for (int r = 0; r < 4; ++r) {
                float s = fmaf(-2.f, acc[r][c], eq);
                if (s < bs[r]) { bs[r] = s; bk[r] = k; }
            }
        }
    }

    // Cross-thread argmin reduction over the 16 cg lanes sharing each row.
    __syncthreads();
    float* rs    = cbs;                       // [TM][16] scores
    int*   ri    = (int*)(cbs + TM * 16);     // [TM][16] indices
    int*   bestk = (int*)(cbs + 2 * TM * 16); // [TM]
#pragma unroll
    for (int r = 0; r < 4; ++r) {
        rs[(4 * rg + r) * 16 + cg] = bs[r];
        ri[(4 * rg + r) * 16 + cg] = bk[r];
    }
    __syncthreads();
    if (tid < TM) {
        float best = rs[tid * 16];
        int   kb   = ri[tid * 16];
        for (int j = 1; j < 16; ++j) {
            float v = rs[tid * 16 + j];
            int   kv = ri[tid * 16 + j];
            if (v < best || (v == best && kv < kb)) { best = v; kb = kv; }
        }
        bestk[tid] = kb;
    }
    __syncthreads();

    // Epilogue: gather codebook rows, straight-through quantize, mask, loss.
    float lsum = 0.f;
    for (int it = 0; it < TM; ++it) {
        int row = r0 + it;
        int k   = bestk[it];
        float zv = zs[tid * ZP + it];
        float e  = __ldg(&cb[(size_t)k * Dd + tid]);
        float d1 = e - zv;         // mimic fp32 rounding of reference's (embed - z)
        float q  = zv + d1;        // quantized (pre-mask)
        float lq = q - zv;         // loss term uses pre-mask quantized
        lsum = fmaf(lq, lq, lsum);
        int mk = read_mask(mask, row, mflag);
        out_q[(size_t)row * Dd + tid] = mk ? q : 0.f;
    }
    if (write_idx && tid < TM) {
        int row = r0 + tid;
        int mk  = read_mask(mask, row, mflag);
        out_i[row] = mk ? (float)bestk[tid] : -1.0f;
    }

    // Block-reduce loss, then one atomic per block.
#pragma unroll
    for (int off = 16; off > 0; off >>= 1)
        lsum += __shfl_down_sync(0xFFFFFFFFu, lsum, off);
    __syncthreads();               // done with rs region
    float* wsum = rs;              // [8] per-warp partials
    if ((tid & 31) == 0) wsum[tid >> 5] = lsum;
    __syncthreads();
    if (tid == 0) {
        float t = 0.f;
        for (int w = 0; w < 8; ++w) t += wsum[w];
        atomicAdd(&g_loss, (double)t);
    }
}

__global__ void fin_k(float* out_loss) {
    out_loss[0] = (float)(0.25 * g_loss / (double)((size_t)ROWS * Dd));
}

extern "C" void kernel_launch(void* const* d_in, const int* in_sizes, int n_in,
                              void* d_out, int out_size) {
    const float* z    = (const float*)d_in[0];
    const void*  mask = d_in[1];
    const float* cb   = (const float*)d_in[2];

    float* out   = (float*)d_out;
    float* out_q = out;
    float* out_i = out + (size_t)ROWS * Dd;
    float* out_l = out_i + ROWS;

    const int need_full = (out_size >= (int)((size_t)ROWS * Dd + ROWS + 1));
    const int smem = (Dd * ZP + TD * CP) * (int)sizeof(float);

    cudaFuncSetAttribute(vq_main, cudaFuncAttributeMaxDynamicSharedMemorySize, smem);

    init_k<<<1, 1>>>();
    detect_k<<<16, 256>>>((const unsigned int*)mask);
    esq_k<<<2, 256>>>(cb);
    vq_main<<<NBLK, 256, smem>>>(z, mask, cb, out_q, out_i, need_full);
    if (need_full) fin_k<<<1, 1>>>(out_l);
}